// round 13
// baseline (speedup 1.0000x reference)
// CrossLayerTranscoder — tf32 mma.sync GEMM. R13: TK=16 + pitch-20 padded rows
// shrinks a stage to 20KB so 3-stage deep prefetch (R7), zero-ALU reg+imm
// addressing (R10) and 3 CTAs/SM TLP (R12) fit together: 60KB x 3 CTAs = 184KB.
// Single barrier/iter, load(i+2) issued right after it (prefetch distance 2).
//
// encode: feats[l] = relu(resid[l] @ enc_w[l]^T)            M=2048,N=512,K=2048
// decode: recon[t] = sum_{s<=t} feats[s] @ dec_w[s,t]^T     M=2048,N=2048,K=(t+1)*512
//
// CTA 128x128x16, 128 threads, 4 warps of 64x64.

#include <cuda_runtime.h>
#include <cstdint>
#include <cstddef>

#define L_DIM 16
#define BS_DIM 2048
#define H_DIM 2048
#define F_DIM 512

#define TM 128
#define TN 128
#define TK 16
#define STAGES 3
#define NTHREADS 128

#define ROW_BYTES 80                         // 20 floats: conflict-free pad
#define TILE_BYTES (TM * ROW_BYTES)          // 10240
#define STAGE_BYTES (2 * TILE_BYTES)         // 20480
#define SMEM_BYTES (STAGES * STAGE_BYTES)    // 61440 (x3 CTAs = 184 KB)

__device__ __forceinline__ uint32_t smem_u32(const void* p) {
    uint32_t a;
    asm("{ .reg .u64 t; cvta.to.shared.u64 t, %1; cvt.u32.u64 %0, t; }" : "=r"(a) : "l"(p));
    return a;
}
__device__ __forceinline__ void cp_async16(uint32_t dst, const float* src) {
    asm volatile("cp.async.cg.shared.global [%0], [%1], 16;" :: "r"(dst), "l"(src));
}
__device__ __forceinline__ void cp_commit() { asm volatile("cp.async.commit_group;"); }
template <int N> __device__ __forceinline__ void cp_wait() {
    asm volatile("cp.async.wait_group %0;" :: "n"(N));
}
// LDS + RNA convert; address = base_reg + folded constant -> LDS [r+imm]
__device__ __forceinline__ uint32_t ldtf32(uint32_t addr) {
    float v; uint32_t r;
    asm volatile("ld.shared.f32 %0, [%1];" : "=f"(v) : "r"(addr));
    asm("cvt.rna.tf32.f32 %0, %1;" : "=r"(r) : "f"(v));
    return r;
}
__device__ __forceinline__ void mma_tf32(float* c, const uint32_t* a, const uint32_t* b) {
    asm volatile(
        "mma.sync.aligned.m16n8k8.row.col.f32.tf32.tf32.f32 "
        "{%0,%1,%2,%3}, {%4,%5,%6,%7}, {%8,%9}, {%0,%1,%2,%3};"
        : "+f"(c[0]), "+f"(c[1]), "+f"(c[2]), "+f"(c[3])
        : "r"(a[0]), "r"(a[1]), "r"(a[2]), "r"(a[3]), "r"(b[0]), "r"(b[1]));
}

template <bool ENCODE>
__global__ __launch_bounds__(NTHREADS, 3)
void clt_gemm(const float* __restrict__ gA, const float* __restrict__ gB,
              float* __restrict__ gOut) {
    extern __shared__ float smem[];
    const uint32_t sbase = smem_u32(smem);
    const int tid  = threadIdx.x;
    const int lane = tid & 31;
    const int w    = tid >> 5;
    const int wm   = w & 1;        // 2 warps along M (64 rows)
    const int wn   = w >> 1;       // 2 warps along N (64 cols)
    const int r8   = lane >> 2;
    const int t    = lane & 3;
    const int m0   = blockIdx.x * TM;
    const int n0   = blockIdx.y * TN;
    const int z    = (int)gridDim.z - 1 - (int)blockIdx.z;   // heavy z first
    const int iters = ENCODE ? (H_DIM / TK) : ((z + 1) * (F_DIM / TK));
    const int LD   = ENCODE ? H_DIM : F_DIM;   // compile-time row pitch

    float acc[4][8][4];
    #pragma unroll
    for (int mt = 0; mt < 4; mt++)
        #pragma unroll
        for (int nt = 0; nt < 8; nt++)
            #pragma unroll
            for (int r = 0; r < 4; r++) acc[mt][nt][r] = 0.0f;

    // ---------- producer: chunk q = j*128 + tid, row = j*32 + (tid>>2), c = tid&3 ----
    // Warp = 8 rows x 64B contiguous (4 chunks each): sector-efficient; the
    // adjacent k-stage completes each 128B line while it is still L2-resident.
    const int rr = tid >> 2;        // 0..31
    const int c4 = tid & 3;         // chunk within row
    const float* pA;
    const float* pB;
    if (ENCODE) {
        pA = gA + ((size_t)z * BS_DIM + m0 + rr) * H_DIM + c4 * 4;
        pB = gB + ((size_t)z * F_DIM + n0 + rr) * H_DIM + c4 * 4;
    } else {
        pA = gA + (size_t)(m0 + rr) * F_DIM + c4 * 4;               // feats[0]
        pB = gB + ((size_t)z * H_DIM + n0 + rr) * F_DIM + c4 * 4;   // dec_w[0][z]
    }
    const uint32_t dst0 = (uint32_t)rr * ROW_BYTES + (uint32_t)c4 * 16;
    int fi = 0;
    auto load_stage = [&]() {
        const int slot = fi % STAGES;
        uint32_t dA = sbase + (uint32_t)slot * STAGE_BYTES + dst0;
        uint32_t dB = dA + TILE_BYTES;
        #pragma unroll
        for (int j = 0; j < 4; j++)     // rows j*32 + rr
            cp_async16(dA + (uint32_t)j * (32 * ROW_BYTES), pA + (size_t)j * 32 * LD);
        #pragma unroll
        for (int j = 0; j < 4; j++)
            cp_async16(dB + (uint32_t)j * (32 * ROW_BYTES), pB + (size_t)j * 32 * LD);
        cp_commit();
        if (ENCODE) { pA += TK; pB += TK; }
        else {
            bool roll = (fi & 31) == 31;   // advance source layer s (32 iters each)
            pA += roll ? ((size_t)BS_DIM * F_DIM - 31 * TK) : TK;
            pB += roll ? ((size_t)L_DIM * H_DIM * F_DIM - 31 * TK) : TK;
        }
        fi++;
    };

    // ---------- per-thread fragment base offsets (bytes within tile) ----------
    // bank = (20*r8 + t) mod 32: all 32 lanes distinct -> conflict-free LDS.
    const uint32_t rowA = (uint32_t)(wm * 64 + r8) * ROW_BYTES + (uint32_t)t * 4;
    const uint32_t rowB = (uint32_t)(wn * 64 + r8) * ROW_BYTES + (uint32_t)t * 4;

    // ---------- prologue: fill STAGES-1 stages ----------
    load_stage();
    load_stage();

    // ---------- mainloop: single barrier/iter, deep prefetch ----------
    for (int i = 0; i < iters; i++) {
        cp_wait<STAGES - 2>();
        __syncthreads();   // stage i visible; slot (i+2)%3 free (compute(i-1) done)
        if (fi < iters) load_stage();

        const uint32_t aslot = sbase + (uint32_t)(i % STAGES) * STAGE_BYTES;
        const uint32_t abase = aslot + rowA;
        const uint32_t bbase = aslot + TILE_BYTES + rowB;

        #pragma unroll
        for (int ks = 0; ks < 2; ks++) {   // TK=16 -> 2 k-steps
            uint32_t af[4][4], bf[8][2];
            #pragma unroll
            for (int mt = 0; mt < 4; mt++) {
                af[mt][0] = ldtf32(abase + (uint32_t)(mt * 1280 +       ks * 32));
                af[mt][1] = ldtf32(abase + (uint32_t)(mt * 1280 + 640 + ks * 32));
                af[mt][2] = ldtf32(abase + (uint32_t)(mt * 1280 +       ks * 32 + 16));
                af[mt][3] = ldtf32(abase + (uint32_t)(mt * 1280 + 640 + ks * 32 + 16));
            }
            #pragma unroll
            for (int nt = 0; nt < 8; nt++) {
                bf[nt][0] = ldtf32(bbase + (uint32_t)(nt * 640 + ks * 32));
                bf[nt][1] = ldtf32(bbase + (uint32_t)(nt * 640 + ks * 32 + 16));
            }
            #pragma unroll
            for (int mt = 0; mt < 4; mt++)
                #pragma unroll
                for (int nt = 0; nt < 8; nt++)
                    mma_tf32(acc[mt][nt], af[mt], bf[nt]);
        }
    }

    // ---------- epilogue: direct float2 stores ----------
    const int ldo = ENCODE ? F_DIM : H_DIM;
    float* ob = gOut + (size_t)z * BS_DIM * ldo;
    #pragma unroll
    for (int mt = 0; mt < 4; mt++) {
        #pragma unroll
        for (int nt = 0; nt < 8; nt++) {
            int row = m0 + wm * 64 + mt * 16 + r8;
            int col = n0 + wn * 64 + nt * 8 + t * 2;
            float v0 = acc[mt][nt][0], v1 = acc[mt][nt][1];
            float v2 = acc[mt][nt][2], v3 = acc[mt][nt][3];
            if (ENCODE) {
                v0 = fmaxf(v0, 0.0f); v1 = fmaxf(v1, 0.0f);
                v2 = fmaxf(v2, 0.0f); v3 = fmaxf(v3, 0.0f);
            }
            *(float2*)&ob[(size_t)row * ldo + col]       = make_float2(v0, v1);
            *(float2*)&ob[(size_t)(row + 8) * ldo + col] = make_float2(v2, v3);
        }
    }
}

extern "C" void kernel_launch(void* const* d_in, const int* in_sizes, int n_in,
                              void* d_out, int out_size) {
    (void)in_sizes; (void)n_in; (void)out_size;
    const float* resid = (const float*)d_in[0];   // [L, B, S, H]
    const float* enc_w = (const float*)d_in[1];   // [L, F, H]
    const float* dec_w = (const float*)d_in[2];   // [L, L, H, F]
    float* out   = (float*)d_out;
    float* feats = out;                                   // [L, BS, F]
    float* recon = out + (size_t)L_DIM * BS_DIM * F_DIM;  // [L, BS, H]

    cudaFuncSetAttribute(clt_gemm<true>,  cudaFuncAttributeMaxDynamicSharedMemorySize, SMEM_BYTES);
    cudaFuncSetAttribute(clt_gemm<false>, cudaFuncAttributeMaxDynamicSharedMemorySize, SMEM_BYTES);

    dim3 grid_enc(BS_DIM / TM, F_DIM / TN, L_DIM);   // 16 x 4 x 16
    clt_gemm<true><<<grid_enc, NTHREADS, SMEM_BYTES>>>(resid, enc_w, feats);

    dim3 grid_dec(BS_DIM / TM, H_DIM / TN, L_DIM);   // 16 x 16 x 16
    clt_gemm<false><<<grid_dec, NTHREADS, SMEM_BYTES>>>(feats, dec_w, recon);
}

// round 14
// speedup vs baseline: 1.2409x; 1.2409x over previous
// CrossLayerTranscoder — tf32 mma.sync GEMM. R14: SMEM-port-ratio fix.
// Port model (matches R7/R8's 66.5% tensor exactly): 128x128 tile needs
// 768 port-cyc (64KB frag reads + 32KB cp.async writes) per 512 tensor-cyc
// -> 66.7% ceiling. 128x256 tile with 8 warps (2Mx4N of 64x64): 1408 port-cyc
// per 1024 tensor-cyc -> 72.7% ceiling. XOR addressing + incremental coalesced
// loader + single barrier/iter + reversed z (all proven) retained.
//
// encode: feats[l] = relu(resid[l] @ enc_w[l]^T)            M=2048,N=512,K=2048
// decode: recon[t] = sum_{s<=t} feats[s] @ dec_w[s,t]^T     M=2048,N=2048,K=(t+1)*512
//
// CTA 128x256x32, 3-stage cp.async (144KB), 256 threads, 1 CTA/SM (8 warps).

#include <cuda_runtime.h>
#include <cstdint>
#include <cstddef>

#define L_DIM 16
#define BS_DIM 2048
#define H_DIM 2048
#define F_DIM 512

#define TM 128
#define TN 256
#define TK 32
#define STAGES 3
#define NTHREADS 256

#define A_BYTES 16384                        // TM*TK*4
#define B_BYTES 32768                        // TN*TK*4
#define STAGE_BYTES (A_BYTES + B_BYTES)      // 49152
#define SMEM_BYTES (STAGES * STAGE_BYTES)    // 147456

__device__ __forceinline__ uint32_t smem_u32(const void* p) {
    uint32_t a;
    asm("{ .reg .u64 t; cvta.to.shared.u64 t, %1; cvt.u32.u64 %0, t; }" : "=r"(a) : "l"(p));
    return a;
}
__device__ __forceinline__ void cp_async16(uint32_t dst, const float* src) {
    asm volatile("cp.async.cg.shared.global [%0], [%1], 16;" :: "r"(dst), "l"(src));
}
__device__ __forceinline__ void cp_commit() { asm volatile("cp.async.commit_group;"); }
template <int N> __device__ __forceinline__ void cp_wait() {
    asm volatile("cp.async.wait_group %0;" :: "n"(N));
}
__device__ __forceinline__ uint32_t ldtf32(uint32_t addr) {
    float v; uint32_t r;
    asm volatile("ld.shared.f32 %0, [%1];" : "=f"(v) : "r"(addr));
    asm("cvt.rna.tf32.f32 %0, %1;" : "=r"(r) : "f"(v));
    return r;
}
__device__ __forceinline__ void mma_tf32(float* c, const uint32_t* a, const uint32_t* b) {
    asm volatile(
        "mma.sync.aligned.m16n8k8.row.col.f32.tf32.tf32.f32 "
        "{%0,%1,%2,%3}, {%4,%5,%6,%7}, {%8,%9}, {%0,%1,%2,%3};"
        : "+f"(c[0]), "+f"(c[1]), "+f"(c[2]), "+f"(c[3])
        : "r"(a[0]), "r"(a[1]), "r"(a[2]), "r"(a[3]), "r"(b[0]), "r"(b[1]));
}

// SMEM tile layout (XOR swizzle, 32 floats/row, 8x16B chunks/row):
// chunk = (k>>2) ^ (row&7), word = k&3. Conflict-free for cp.async row writes
// and fragment LDS. Fragment addr = rowbase ^ ((2ks)<<4); k+4 variant ^16
// (row&7 == r8 for every fragment row).

template <bool ENCODE>
__global__ __launch_bounds__(NTHREADS, 1)
void clt_gemm(const float* __restrict__ gA, const float* __restrict__ gB,
              float* __restrict__ gOut) {
    extern __shared__ float smem[];
    const uint32_t sbase = smem_u32(smem);
    const int tid  = threadIdx.x;
    const int lane = tid & 31;
    const int w    = tid >> 5;
    const int wm   = w & 1;        // 2 warps along M (64 rows each)
    const int wn   = w >> 1;       // 4 warps along N (64 cols each)
    const int r8   = lane >> 2;
    const int t    = lane & 3;
    const int m0   = blockIdx.x * TM;
    const int n0   = blockIdx.y * TN;
    const int z    = (int)gridDim.z - 1 - (int)blockIdx.z;   // heavy z first
    const int iters = ENCODE ? (H_DIM / TK) : ((z + 1) * (F_DIM / TK));
    const int LD   = ENCODE ? H_DIM : F_DIM;   // compile-time row pitch

    float acc[4][8][4];
    #pragma unroll
    for (int mt = 0; mt < 4; mt++)
        #pragma unroll
        for (int nt = 0; nt < 8; nt++)
            #pragma unroll
            for (int r = 0; r < 4; r++) acc[mt][nt][r] = 0.0f;

    // ---------- producer (coalesced, incremental) ----------
    // chunk q = j*256 + tid: row = j*32 + (tid>>3), chunk col = tid&7.
    // A: j=0..3 (128 rows), B: j=0..7 (256 rows). row&7 = (tid>>3)&7 const,
    // so smem dst and gmem src are constant offsets from incremental pointers.
    const int tid8 = tid >> 3;      // 0..31
    const int cch  = tid & 7;
    const float* pA;
    const float* pB;
    if (ENCODE) {
        pA = gA + ((size_t)z * BS_DIM + m0 + tid8) * H_DIM + cch * 4;
        pB = gB + ((size_t)z * F_DIM + n0 + tid8) * H_DIM + cch * 4;
    } else {
        pA = gA + (size_t)(m0 + tid8) * F_DIM + cch * 4;               // feats[0]
        pB = gB + ((size_t)z * H_DIM + n0 + tid8) * F_DIM + cch * 4;   // dec_w[0][z]
    }
    const uint32_t dst0 = (uint32_t)tid8 * 128 + ((uint32_t)(cch ^ (tid8 & 7)) << 4);
    int fi = 0;
    auto load_stage = [&]() {
        const int slot = fi % STAGES;
        uint32_t dA = sbase + (uint32_t)slot * STAGE_BYTES + dst0;
        uint32_t dB = dA + A_BYTES;
        #pragma unroll
        for (int j = 0; j < 4; j++)     // A rows j*32 + tid8
            cp_async16(dA + (uint32_t)j * 4096, pA + (size_t)j * 32 * LD);
        #pragma unroll
        for (int j = 0; j < 8; j++)     // B rows j*32 + tid8
            cp_async16(dB + (uint32_t)j * 4096, pB + (size_t)j * 32 * LD);
        cp_commit();
        if (ENCODE) { pA += TK; pB += TK; }
        else {
            bool roll = (fi & 15) == 15;   // advance source layer s
            pA += roll ? ((size_t)BS_DIM * F_DIM - 15 * TK) : TK;
            pB += roll ? ((size_t)L_DIM * H_DIM * F_DIM - 15 * TK) : TK;
        }
        fi++;
    };

    // ---------- consumer rowbase offsets (bytes within tile) ----------
    uint32_t rbA[4][2], rbB[8];
    #pragma unroll
    for (int mt = 0; mt < 4; mt++) {
        int r = wm * 64 + mt * 16 + r8;
        rbA[mt][0] = (uint32_t)r * 128 + ((uint32_t)r8 << 4) + (uint32_t)t * 4;
        rbA[mt][1] = rbA[mt][0] + 8 * 128;
    }
    #pragma unroll
    for (int nt = 0; nt < 8; nt++) {
        int n = wn * 64 + nt * 8 + r8;
        rbB[nt] = (uint32_t)n * 128 + ((uint32_t)r8 << 4) + (uint32_t)t * 4;
    }

    // ---------- prologue ----------
    load_stage();
    load_stage();

    // ---------- mainloop: single barrier per iteration ----------
    for (int i = 0; i < iters; i++) {
        cp_wait<STAGES - 2>();
        __syncthreads();
        if (fi < iters) load_stage();

        const uint32_t aslot = sbase + (uint32_t)(i % STAGES) * STAGE_BYTES;
        const uint32_t bslot = aslot + A_BYTES;

        #pragma unroll
        for (int ks = 0; ks < 4; ks++) {
            const uint32_t x0 = (uint32_t)(2 * ks) << 4;
            uint32_t af[4][4], bf[8][2];
            #pragma unroll
            for (int mt = 0; mt < 4; mt++) {
                uint32_t b0 = aslot + rbA[mt][0];
                uint32_t b1 = aslot + rbA[mt][1];
                af[mt][0] = ldtf32(b0 ^ x0);
                af[mt][1] = ldtf32(b1 ^ x0);
                af[mt][2] = ldtf32(b0 ^ (x0 | 16u));
                af[mt][3] = ldtf32(b1 ^ (x0 | 16u));
            }
            #pragma unroll
            for (int nt = 0; nt < 8; nt++) {
                uint32_t bb = bslot + rbB[nt];
                bf[nt][0] = ldtf32(bb ^ x0);
                bf[nt][1] = ldtf32(bb ^ (x0 | 16u));
            }
            #pragma unroll
            for (int mt = 0; mt < 4; mt++)
                #pragma unroll
                for (int nt = 0; nt < 8; nt++)
                    mma_tf32(acc[mt][nt], af[mt], bf[nt]);
        }
    }

    // ---------- epilogue: direct float2 stores ----------
    const int ldo = ENCODE ? F_DIM : H_DIM;
    float* ob = gOut + (size_t)z * BS_DIM * ldo;
    #pragma unroll
    for (int mt = 0; mt < 4; mt++) {
        #pragma unroll
        for (int nt = 0; nt < 8; nt++) {
            int row = m0 + wm * 64 + mt * 16 + r8;
            int col = n0 + wn * 64 + nt * 8 + t * 2;
            float v0 = acc[mt][nt][0], v1 = acc[mt][nt][1];
            float v2 = acc[mt][nt][2], v3 = acc[mt][nt][3];
            if (ENCODE) {
                v0 = fmaxf(v0, 0.0f); v1 = fmaxf(v1, 0.0f);
                v2 = fmaxf(v2, 0.0f); v3 = fmaxf(v3, 0.0f);
            }
            *(float2*)&ob[(size_t)row * ldo + col]       = make_float2(v0, v1);
            *(float2*)&ob[(size_t)(row + 8) * ldo + col] = make_float2(v2, v3);
        }
    }
}

extern "C" void kernel_launch(void* const* d_in, const int* in_sizes, int n_in,
                              void* d_out, int out_size) {
    (void)in_sizes; (void)n_in; (void)out_size;
    const float* resid = (const float*)d_in[0];   // [L, B, S, H]
    const float* enc_w = (const float*)d_in[1];   // [L, F, H]
    const float* dec_w = (const float*)d_in[2];   // [L, L, H, F]
    float* out   = (float*)d_out;
    float* feats = out;                                   // [L, BS, F]
    float* recon = out + (size_t)L_DIM * BS_DIM * F_DIM;  // [L, BS, H]

    cudaFuncSetAttribute(clt_gemm<true>,  cudaFuncAttributeMaxDynamicSharedMemorySize, SMEM_BYTES);
    cudaFuncSetAttribute(clt_gemm<false>, cudaFuncAttributeMaxDynamicSharedMemorySize, SMEM_BYTES);

    dim3 grid_enc(BS_DIM / TM, F_DIM / TN, L_DIM);   // 16 x 2 x 16
    clt_gemm<true><<<grid_enc, NTHREADS, SMEM_BYTES>>>(resid, enc_w, feats);

    dim3 grid_dec(BS_DIM / TM, H_DIM / TN, L_DIM);   // 16 x 8 x 16
    clt_gemm<false><<<grid_dec, NTHREADS, SMEM_BYTES>>>(feats, dec_w, recon);
}

// round 15
// speedup vs baseline: 1.4985x; 1.2075x over previous
// CrossLayerTranscoder — tf32 mma.sync GEMM. R15 = R7 champion config
// (128x128 CTA, 4 warps of 64x64, 2 CTAs/SM, 3-stage cp.async, XOR swizzle)
// + ldmatrix.m8n8.x4.b16 fragment loads: 128 LDS.32 -> 32 LDSM per warp-iter,
// 4x fewer dependency heads and 4x fewer swizzle LOP3s. f32 elements ride the
// b16 ldmatrix as column pairs; lane->row mapping makes the x4 sub-tiles land
// exactly as mma {a0,a1,a2,a3} / {b0,b1}x2. XOR commutes: addr = base^(ks<<5).
//
// encode: feats[l] = relu(resid[l] @ enc_w[l]^T)            M=2048,N=512,K=2048
// decode: recon[t] = sum_{s<=t} feats[s] @ dec_w[s,t]^T     M=2048,N=2048,K=(t+1)*512

#include <cuda_runtime.h>
#include <cstdint>
#include <cstddef>

#define L_DIM 16
#define BS_DIM 2048
#define H_DIM 2048
#define F_DIM 512

#define TM 128
#define TN 128
#define TK 32
#define STAGES 3
#define NTHREADS 128

#define A_BYTES 16384                        // TM*TK*4
#define STAGE_BYTES 32768                    // A + B
#define SMEM_BYTES (STAGES * STAGE_BYTES)    // 96 KB (x2 CTAs = 192 KB)

__device__ __forceinline__ uint32_t smem_u32(const void* p) {
    uint32_t a;
    asm("{ .reg .u64 t; cvta.to.shared.u64 t, %1; cvt.u32.u64 %0, t; }" : "=r"(a) : "l"(p));
    return a;
}
__device__ __forceinline__ void cp_async16(uint32_t dst, const float* src) {
    asm volatile("cp.async.cg.shared.global [%0], [%1], 16;" :: "r"(dst), "l"(src));
}
__device__ __forceinline__ void cp_commit() { asm volatile("cp.async.commit_group;"); }
template <int N> __device__ __forceinline__ void cp_wait() {
    asm volatile("cp.async.wait_group %0;" :: "n"(N));
}
__device__ __forceinline__ void ldsm4(uint32_t* r, uint32_t addr) {
    asm volatile("ldmatrix.sync.aligned.m8n8.x4.shared.b16 {%0,%1,%2,%3}, [%4];"
                 : "=r"(r[0]), "=r"(r[1]), "=r"(r[2]), "=r"(r[3]) : "r"(addr));
}
__device__ __forceinline__ uint32_t cvt_tf32(uint32_t x) {
    uint32_t r; float f = __uint_as_float(x);
    asm("cvt.rna.tf32.f32 %0, %1;" : "=r"(r) : "f"(f));
    return r;
}
__device__ __forceinline__ void mma_tf32(float* c, const uint32_t* a, const uint32_t* b) {
    asm volatile(
        "mma.sync.aligned.m16n8k8.row.col.f32.tf32.tf32.f32 "
        "{%0,%1,%2,%3}, {%4,%5,%6,%7}, {%8,%9}, {%0,%1,%2,%3};"
        : "+f"(c[0]), "+f"(c[1]), "+f"(c[2]), "+f"(c[3])
        : "r"(a[0]), "r"(a[1]), "r"(a[2]), "r"(a[3]), "r"(b[0]), "r"(b[1]));
}

// SMEM tile layout (XOR swizzle): addr(row,k) = row*128 + ((k>>2 ^ (row&7))<<4)
// + (k&3)*4. k-group g = k>>2; per-lane ldmatrix base uses g = glane, and the
// ks-dependent group 2ks+glane XORs in as base ^ (ks<<5).

template <bool ENCODE>
__global__ __launch_bounds__(NTHREADS, 2)
void clt_gemm(const float* __restrict__ gA, const float* __restrict__ gB,
              float* __restrict__ gOut) {
    extern __shared__ float smem[];
    const uint32_t sbase = smem_u32(smem);
    const int tid  = threadIdx.x;
    const int lane = tid & 31;
    const int w    = tid >> 5;
    const int wm   = w & 1;        // 2 warps along M (64 rows)
    const int wn   = w >> 1;       // 2 warps along N (64 cols)
    const int r8   = lane >> 2;
    const int t    = lane & 3;
    const int m0   = blockIdx.x * TM;
    const int n0   = blockIdx.y * TN;
    const int z    = (int)gridDim.z - 1 - (int)blockIdx.z;   // heavy z first
    const int iters = ENCODE ? (H_DIM / TK) : ((z + 1) * (F_DIM / TK));
    const int LD   = ENCODE ? H_DIM : F_DIM;   // compile-time row pitch

    float acc[4][8][4];
    #pragma unroll
    for (int mt = 0; mt < 4; mt++)
        #pragma unroll
        for (int nt = 0; nt < 8; nt++)
            #pragma unroll
            for (int r = 0; r < 4; r++) acc[mt][nt][r] = 0.0f;

    // ---------- producer (coalesced, incremental; unchanged from R7) ----------
    const int tid8 = tid >> 3;
    const int cch  = tid & 7;
    const float* pA;
    const float* pB;
    if (ENCODE) {
        pA = gA + ((size_t)z * BS_DIM + m0 + tid8) * H_DIM + cch * 4;
        pB = gB + ((size_t)z * F_DIM + n0 + tid8) * H_DIM + cch * 4;
    } else {
        pA = gA + (size_t)(m0 + tid8) * F_DIM + cch * 4;               // feats[0]
        pB = gB + ((size_t)z * H_DIM + n0 + tid8) * F_DIM + cch * 4;   // dec_w[0][z]
    }
    const uint32_t dst0 = (uint32_t)tid8 * 128 + ((uint32_t)(cch ^ (tid8 & 7)) << 4);
    int fi = 0;
    auto load_stage = [&]() {
        const int slot = fi % STAGES;
        uint32_t dA = sbase + (uint32_t)slot * STAGE_BYTES + dst0;
        uint32_t dB = dA + A_BYTES;
        #pragma unroll
        for (int j = 0; j < 8; j++)
            cp_async16(dA + (uint32_t)j * 2048, pA + (size_t)j * 16 * LD);
        #pragma unroll
        for (int j = 0; j < 8; j++)
            cp_async16(dB + (uint32_t)j * 2048, pB + (size_t)j * 16 * LD);
        cp_commit();
        if (ENCODE) { pA += TK; pB += TK; }
        else {
            bool roll = (fi & 15) == 15;   // advance source layer s
            pA += roll ? ((size_t)BS_DIM * F_DIM - 15 * TK) : TK;
            pB += roll ? ((size_t)L_DIM * H_DIM * F_DIM - 15 * TK) : TK;
        }
        fi++;
    };

    // ---------- per-lane ldmatrix base offsets (bytes within tile) ----------
    // A (per mt): lanes 0-15 -> g=0 rows (lane&15); lanes 16-31 -> g=1, same rows.
    //   sub-tiles land as mma {a0,a1,a2,a3}.
    // B (per nt pair np): lanes (..>>4) pick nt / nt+1 rows, (..>>3)&1 picks g.
    //   regs {r0,r1} = bf[2np], {r2,r3} = bf[2np+1].
    uint32_t lbA[4], lbB[4];
    {
        const int rlA = lane & 15;
        const uint32_t glA = (uint32_t)(lane >> 4);
        #pragma unroll
        for (int mt = 0; mt < 4; mt++) {
            int row = wm * 64 + mt * 16 + rlA;
            lbA[mt] = (uint32_t)row * 128 + ((glA ^ ((uint32_t)row & 7u)) << 4);
        }
        const int rlB = ((lane >> 4) << 3) + (lane & 7);
        const uint32_t glB = (uint32_t)((lane >> 3) & 1);
        #pragma unroll
        for (int np = 0; np < 4; np++) {
            int row = wn * 64 + np * 16 + rlB;
            lbB[np] = (uint32_t)row * 128 + ((glB ^ ((uint32_t)row & 7u)) << 4);
        }
    }

    // ---------- prologue ----------
    load_stage();
    load_stage();

    // ---------- mainloop: single barrier per iteration ----------
    for (int i = 0; i < iters; i++) {
        cp_wait<STAGES - 2>();
        __syncthreads();
        if (fi < iters) load_stage();

        const uint32_t aslot = sbase + (uint32_t)(i % STAGES) * STAGE_BYTES;
        const uint32_t bslot = aslot + A_BYTES;
        uint32_t aB[4], bB[4];
        #pragma unroll
        for (int mt = 0; mt < 4; mt++) aB[mt] = aslot + lbA[mt];
        #pragma unroll
        for (int np = 0; np < 4; np++) bB[np] = bslot + lbB[np];

        #pragma unroll
        for (int ks = 0; ks < 4; ks++) {
            const uint32_t x = (uint32_t)ks << 5;
            uint32_t af[4][4], bfp[4][4];
            #pragma unroll
            for (int mt = 0; mt < 4; mt++) ldsm4(af[mt], aB[mt] ^ x);
            #pragma unroll
            for (int np = 0; np < 4; np++) ldsm4(bfp[np], bB[np] ^ x);
            #pragma unroll
            for (int mt = 0; mt < 4; mt++)
                #pragma unroll
                for (int r = 0; r < 4; r++) af[mt][r] = cvt_tf32(af[mt][r]);
            #pragma unroll
            for (int np = 0; np < 4; np++)
                #pragma unroll
                for (int r = 0; r < 4; r++) bfp[np][r] = cvt_tf32(bfp[np][r]);
            #pragma unroll
            for (int mt = 0; mt < 4; mt++)
                #pragma unroll
                for (int nt = 0; nt < 8; nt++)
                    mma_tf32(acc[mt][nt], af[mt], &bfp[nt >> 1][(nt & 1) * 2]);
        }
    }

    // ---------- epilogue: direct float2 stores ----------
    const int ldo = ENCODE ? F_DIM : H_DIM;
    float* ob = gOut + (size_t)z * BS_DIM * ldo;
    #pragma unroll
    for (int mt = 0; mt < 4; mt++) {
        #pragma unroll
        for (int nt = 0; nt < 8; nt++) {
            int row = m0 + wm * 64 + mt * 16 + r8;
            int col = n0 + wn * 64 + nt * 8 + t * 2;
            float v0 = acc[mt][nt][0], v1 = acc[mt][nt][1];
            float v2 = acc[mt][nt][2], v3 = acc[mt][nt][3];
            if (ENCODE) {
                v0 = fmaxf(v0, 0.0f); v1 = fmaxf(v1, 0.0f);
                v2 = fmaxf(v2, 0.0f); v3 = fmaxf(v3, 0.0f);
            }
            *(float2*)&ob[(size_t)row * ldo + col]       = make_float2(v0, v1);
            *(float2*)&ob[(size_t)(row + 8) * ldo + col] = make_float2(v2, v3);
        }
    }
}

extern "C" void kernel_launch(void* const* d_in, const int* in_sizes, int n_in,
                              void* d_out, int out_size) {
    (void)in_sizes; (void)n_in; (void)out_size;
    const float* resid = (const float*)d_in[0];   // [L, B, S, H]
    const float* enc_w = (const float*)d_in[1];   // [L, F, H]
    const float* dec_w = (const float*)d_in[2];   // [L, L, H, F]
    float* out   = (float*)d_out;
    float* feats = out;                                   // [L, BS, F]
    float* recon = out + (size_t)L_DIM * BS_DIM * F_DIM;  // [L, BS, H]

    cudaFuncSetAttribute(clt_gemm<true>,  cudaFuncAttributeMaxDynamicSharedMemorySize, SMEM_BYTES);
    cudaFuncSetAttribute(clt_gemm<false>, cudaFuncAttributeMaxDynamicSharedMemorySize, SMEM_BYTES);

    dim3 grid_enc(BS_DIM / TM, F_DIM / TN, L_DIM);   // 16 x 4 x 16
    clt_gemm<true><<<grid_enc, NTHREADS, SMEM_BYTES>>>(resid, enc_w, feats);

    dim3 grid_dec(BS_DIM / TM, H_DIM / TN, L_DIM);   // 16 x 16 x 16
    clt_gemm<false><<<grid_dec, NTHREADS, SMEM_BYTES>>>(feats, dec_w, recon);
}